// round 16
// baseline (speedup 1.0000x reference)
#include <cuda_runtime.h>

#define H_ 256
#define W_ 256
#define N_ (H_*W_)
#define B_ 8
#define D_ 12
#define STEPS_ 8
#define TX_ 32
#define TY_ 16
#define SMW_ 35   // padded (32 + 2 halo + 1 pad) to avoid LDS bank conflicts
#define SMH_ 18

// ping-pong hidden-state buffers (12 channels), static device memory (no allocs)
__device__ float g_buf0[B_*D_*N_];
__device__ float g_buf1[B_*D_*N_];

typedef unsigned long long u64;

// packed weights: [(i*10+k)*6+op] = {w[2op], w[2op+1]} ; identity folded into k=4
__constant__ u64   c_w[D_*10*6];
__constant__ float c_b[D_];
__device__   u64   g_wstage[D_*10*6];
__device__   float g_bstage[D_];

__device__ __forceinline__ u64 pk2(float lo, float hi) {
    u64 r; asm("mov.b64 %0, {%1, %2};" : "=l"(r) : "f"(lo), "f"(hi)); return r;
}
__device__ __forceinline__ void fma2(u64& d, u64 a, u64 b) {
    asm("fma.rn.f32x2 %0, %1, %2, %0;" : "+l"(d) : "l"(a), "l"(b));
}
__device__ __forceinline__ u64 add2(u64 a, u64 b) {
    u64 r; asm("add.rn.f32x2 %0, %1, %2;" : "=l"(r) : "l"(a), "l"(b)); return r;
}
__device__ __forceinline__ u64 mul2(u64 a, u64 b) {
    u64 r; asm("mul.rn.f32x2 %0, %1, %2;" : "=l"(r) : "l"(a), "l"(b)); return r;
}
__device__ __forceinline__ void upk2(u64 v, float& lo, float& hi) {
    asm("mov.b64 {%0, %1}, %2;" : "=f"(lo), "=f"(hi) : "l"(v));
}

// Load one smem float into BOTH halves of a register pair: two LDS.32 to the
// same address, no packing MOVs (ptxas allocates lo/hi as the output pair).
__device__ __forceinline__ u64 lds_dup(unsigned a) {
    u64 r;
    asm("{\n\t"
        ".reg .b32 lo, hi;\n\t"
        "ld.shared.b32 lo, [%1];\n\t"
        "ld.shared.b32 hi, [%1];\n\t"
        "mov.b64 %0, {lo, hi};\n\t"
        "}" : "=l"(r) : "r"(a));
    return r;
}

__device__ __forceinline__ float elu_f(float x) {
    return x > 0.f ? x : (__expf(x) - 1.f);
}
__device__ __forceinline__ float sigmoid_f(float x) {
    return __fdividef(1.f, 1.f + __expf(-x));
}

// Pack dup'd weight pairs into staging (copied to __constant__ by the launcher).
__global__ void pack_weights(const float* __restrict__ Wh, const float* __restrict__ bh,
                             const float* __restrict__ Wmp, const float* __restrict__ bmp)
{
    for (int idx = threadIdx.x; idx < D_*10*6; idx += 128) {
        int i  = idx / 60;
        int r  = idx - i*60;
        int k  = r / 6;
        int op = r - k*6;
        int o0 = 2*op, o1 = 2*op + 1;
        float w0, w1;
        if (k < 9) {
            w0 = Wh[(o0*D_ + i)*9 + k] + ((k == 4 && o0 == i) ? 1.f : 0.f);
            w1 = Wh[(o1*D_ + i)*9 + k] + ((k == 4 && o1 == i) ? 1.f : 0.f);
        } else {
            w0 = Wmp[o0*D_ + i];
            w1 = Wmp[o1*D_ + i];
        }
        g_wstage[idx] = pk2(w0, w1);
    }
    if (threadIdx.x < D_) g_bstage[threadIdx.x] = bh[threadIdx.x] + bmp[threadIdx.x];
}

// One NCA step: conv3x3 (+identity folded) + graph MP (10th tap) + elu.
// Round-14 structure (constant-bank weights) with MOV-free dup'd taps
// (double-LDS into register pairs) and fully packed graph-MP math.
__global__ void __launch_bounds__(128, 4) nca_step(
    const float* __restrict__ src, long long src_bs, int src_co,
    float* __restrict__ dst, long long dst_bs, int dst_co)
{
    __shared__ float tile[D_][SMH_][SMW_];   // input tile with 1-px halo

    const int tid = threadIdx.x;
    const int b   = blockIdx.z;
    const int bx0 = blockIdx.x * TX_;
    const int by0 = blockIdx.y * TY_;

    // ---- load input tile (+halo, zero-padded at image border) ----
    const float* sb = src + (long long)b * src_bs + (long long)src_co * N_;
    for (int idx = tid; idx < D_*SMH_*34; idx += 128) {
        int i  = idx / (SMH_*34);
        int r  = idx - i*(SMH_*34);
        int ly = r / 34;
        int lx = r - ly*34;
        int gy = by0 + ly - 1, gx = bx0 + lx - 1;
        float v = 0.f;
        if ((unsigned)gy < H_ && (unsigned)gx < W_)
            v = sb[(long long)i*N_ + gy*W_ + gx];
        tile[i][ly][lx] = v;
    }
    __syncthreads();

    // thread -> one row of 4 x-adjacent pixels: (gy, gx0..gx0+3)
    const int txp = tid & 7;        // 0..7
    const int typ = tid >> 3;       // 0..15
    const int gx0 = bx0 + 4*txp;
    const int gy  = by0 + typ;
    const int lxb = 4*txp;          // halo col of (gx0 - 1)

    u64 dinv2[4];
    {
        int dy = (gy==0) + (gy==H_-1);
        #pragma unroll
        for (int p = 0; p < 4; p++) {
            int gx = gx0 + p;
            float d = 1.f / (float)(4 - dy - (gx==0) - (gx==W_-1));
            dinv2[p] = pk2(d, d);
        }
    }

    u64 acc[6][4];
    #pragma unroll
    for (int op = 0; op < 6; op++)
        #pragma unroll
        for (int p = 0; p < 4; p++) acc[op][p] = 0ull;

    const unsigned tbase = (unsigned)__cvta_generic_to_shared(&tile[0][typ][lxb]);

    #pragma unroll 1
    for (int i = 0; i < D_; i++) {
        const unsigned ta = tbase + (unsigned)(i * (SMH_*SMW_*4));
        u64 d0[6], d1[6], d2[6];
        #pragma unroll
        for (int c = 0; c < 6; c++) {
            d0[c] = lds_dup(ta + c*4);
            d1[c] = lds_dup(ta + (SMW_ + c)*4);
            d2[c] = lds_dup(ta + (2*SMW_ + c)*4);
        }
        u64 nsd[4];
        #pragma unroll
        for (int p = 0; p < 4; p++) {
            // packed 4-neighbor avg: all operands dup'd -> result dup'd
            nsd[p] = mul2(add2(add2(d0[p+1], d2[p+1]), add2(d1[p], d1[p+2])), dinv2[p]);
        }
        const int wbase = i*60;
        #pragma unroll
        for (int k = 0; k < 10; k++) {
            #pragma unroll
            for (int op = 0; op < 6; op++) {
                u64 w = c_w[wbase + k*6 + op];   // uniform const load: no crossbar
                #pragma unroll
                for (int p = 0; p < 4; p++) {
                    u64 tap;
                    if      (k < 3) tap = d0[p + k];
                    else if (k < 6) tap = d1[p + k - 3];
                    else if (k < 9) tap = d2[p + k - 6];
                    else            tap = nsd[p];
                    fma2(acc[op][p], tap, w);
                }
            }
        }
    }

    float* db = dst + (long long)b * dst_bs + (long long)dst_co * N_;
    #pragma unroll
    for (int op = 0; op < 6; op++) {
        float4 s0, s1;
        float b0 = c_b[2*op], b1 = c_b[2*op+1];
        float a, bb;
        upk2(acc[op][0], a, bb); s0.x = elu_f(a + b0); s1.x = elu_f(bb + b1);
        upk2(acc[op][1], a, bb); s0.y = elu_f(a + b0); s1.y = elu_f(bb + b1);
        upk2(acc[op][2], a, bb); s0.z = elu_f(a + b0); s1.z = elu_f(bb + b1);
        upk2(acc[op][3], a, bb); s0.w = elu_f(a + b0); s1.w = elu_f(bb + b1);
        *reinterpret_cast<float4*>(db + (long long)(2*op  )*N_ + gy*W_ + gx0) = s0;
        *reinterpret_cast<float4*>(db + (long long)(2*op+1)*N_ + gy*W_ + gx0) = s1;
    }
}

// Final head: reads hidden (out ch 4..15), computes alive + rgb, writes ch 0..3.
__global__ void __launch_bounds__(256) nca_head(
    float* __restrict__ out,
    const float* __restrict__ Wa, const float* __restrict__ ba,
    const float* __restrict__ Wr1, const float* __restrict__ br1,
    const float* __restrict__ Wr2, const float* __restrict__ br2)
{
    __shared__ float fsm[220];  // Wa(12) ba(1) Wr1(156) br1(12) Wr2(36) br2(3)
    const int tid = threadIdx.x;
    if (tid < 220) {
        float v;
        if (tid < 12)       v = Wa[tid];
        else if (tid == 12) v = ba[0];
        else if (tid < 169) v = Wr1[tid-13];
        else if (tid < 181) v = br1[tid-169];
        else if (tid < 217) v = Wr2[tid-181];
        else                v = br2[tid-217];
        fsm[tid] = v;
    }
    __syncthreads();

    long long pp = (long long)blockIdx.x * 256 + tid;   // pair index, < B*N/2
    int b = (int)(pp / (N_/2));
    int r = (int)(pp - (long long)b * (N_/2));
    float* base = out + (long long)b * 16 * N_ + 2*r;

    float h0[D_], h1[D_];
    #pragma unroll
    for (int c = 0; c < D_; c++) {
        float2 v = *reinterpret_cast<const float2*>(base + (long long)(4+c)*N_);
        h0[c] = v.x; h1[c] = v.y;
    }
    float al0 = fsm[12], al1 = fsm[12];
    #pragma unroll
    for (int c = 0; c < 12; c++) { al0 += fsm[c]*h0[c]; al1 += fsm[c]*h1[c]; }
    al0 = sigmoid_f(al0); al1 = sigmoid_f(al1);
    float r10[12], r11[12];
    #pragma unroll
    for (int j = 0; j < 12; j++) {
        float s0 = fsm[169+j], s1 = s0;
        #pragma unroll
        for (int c = 0; c < 12; c++) { s0 += fsm[13+j*13+c]*h0[c]; s1 += fsm[13+j*13+c]*h1[c]; }
        s0 += fsm[13+j*13+12]*al0;  s1 += fsm[13+j*13+12]*al1;
        r10[j] = s0 > 0.f ? s0 : 0.f;
        r11[j] = s1 > 0.f ? s1 : 0.f;
    }
    float2 sta; sta.x = al0; sta.y = al1;
    *reinterpret_cast<float2*>(base) = sta;              // channel 0: alive
    #pragma unroll
    for (int k = 0; k < 3; k++) {
        float s0 = fsm[217+k], s1 = s0;
        #pragma unroll
        for (int j = 0; j < 12; j++) { s0 += fsm[181+k*12+j]*r10[j]; s1 += fsm[181+k*12+j]*r11[j]; }
        s0 = sigmoid_f(s0)*al0;  s1 = sigmoid_f(s1)*al1;
        float2 st; st.x = s0; st.y = s1;
        *reinterpret_cast<float2*>(base + (long long)(1+k)*N_) = st;  // ch 1..3: rgb
    }
}

extern "C" void kernel_launch(void* const* d_in, const int* in_sizes, int n_in,
                              void* d_out, int out_size) {
    const float* x = (const float*)d_in[0];
    // locate weights by size: Wh has 12*12*9 = 1296 elements
    int wb = 1;
    while (wb < n_in && in_sizes[wb] != 1296) wb++;
    const float* Wh  = (const float*)d_in[wb+0];
    const float* bh  = (const float*)d_in[wb+1];
    const float* Wmp = (const float*)d_in[wb+2];
    const float* bmp = (const float*)d_in[wb+3];
    const float* Wa  = (const float*)d_in[wb+4];
    const float* ba  = (const float*)d_in[wb+5];
    const float* Wr1 = (const float*)d_in[wb+6];
    const float* br1 = (const float*)d_in[wb+7];
    const float* Wr2 = (const float*)d_in[wb+8];
    const float* br2 = (const float*)d_in[wb+9];
    float* out = (float*)d_out;

    float *bp0, *bp1;
    cudaGetSymbolAddress((void**)&bp0, g_buf0);
    cudaGetSymbolAddress((void**)&bp1, g_buf1);

    // pack weights once, then copy into the constant bank (D2D, graph-capturable)
    pack_weights<<<1, 128>>>(Wh, bh, Wmp, bmp);
    void* wstage; void* bstage;
    cudaGetSymbolAddress(&wstage, g_wstage);
    cudaGetSymbolAddress(&bstage, g_bstage);
    cudaMemcpyToSymbolAsync(c_w, wstage, sizeof(u64)*D_*10*6, 0, cudaMemcpyDeviceToDevice, 0);
    cudaMemcpyToSymbolAsync(c_b, bstage, sizeof(float)*D_, 0, cudaMemcpyDeviceToDevice, 0);

    dim3 grid(W_/TX_, H_/TY_, B_);
    dim3 blk(128);

    const float* src = x;
    long long sbs = 16LL*N_; int sco = 4;
    for (int s = 0; s < STEPS_; s++) {
        int fin = (s == STEPS_-1);
        float* dst; long long dbs; int dco;
        if (fin) { dst = out; dbs = 16LL*N_; dco = 4; }
        else     { dst = (s & 1) ? bp1 : bp0; dbs = 12LL*N_; dco = 0; }
        nca_step<<<grid, blk>>>(src, sbs, sco, dst, dbs, dco);
        src = dst; sbs = dbs; sco = dco;
    }
    // head epilogue: fills out channels 0..3 from hidden in channels 4..15
    nca_head<<<(B_*N_/2)/256, 256>>>(out, Wa, ba, Wr1, br1, Wr2, br2);
}

// round 17
// speedup vs baseline: 1.2053x; 1.2053x over previous
#include <cuda_runtime.h>

#define H_ 256
#define W_ 256
#define N_ (H_*W_)
#define B_ 8
#define D_ 12
#define STEPS_ 8
#define TX_ 32
#define TY_ 16
#define SMW_ 35   // padded (32 + 2 halo + 1 pad) to avoid LDS bank conflicts
#define SMH_ 18

// ping-pong hidden-state buffers (12 channels), static device memory (no allocs)
__device__ float g_buf0[B_*D_*N_];
__device__ float g_buf1[B_*D_*N_];

typedef unsigned long long u64;

// packed weights: [(i*10+k)*6+op] = {w[2op], w[2op+1]} ; identity folded into k=4
// 16-byte aligned pairs: (op even) -> ld.const.v2.u64 loads two channel-pairs.
__constant__ u64   c_w[D_*10*6];
__constant__ float c_b[D_];
__device__   u64   g_wstage[D_*10*6];
__device__   float g_bstage[D_];

__device__ __forceinline__ u64 pk2(float lo, float hi) {
    u64 r; asm("mov.b64 %0, {%1, %2};" : "=l"(r) : "f"(lo), "f"(hi)); return r;
}
__device__ __forceinline__ void fma2(u64& d, u64 a, u64 b) {
    asm("fma.rn.f32x2 %0, %1, %2, %0;" : "+l"(d) : "l"(a), "l"(b));
}
__device__ __forceinline__ void upk2(u64 v, float& lo, float& hi) {
    asm("mov.b64 {%0, %1}, %2;" : "=f"(lo), "=f"(hi) : "l"(v));
}

__device__ __forceinline__ float elu_f(float x) {
    return x > 0.f ? x : (__expf(x) - 1.f);
}
__device__ __forceinline__ float sigmoid_f(float x) {
    return __fdividef(1.f, 1.f + __expf(-x));
}

// Pack dup'd weight pairs into staging (copied to __constant__ by the launcher).
__global__ void pack_weights(const float* __restrict__ Wh, const float* __restrict__ bh,
                             const float* __restrict__ Wmp, const float* __restrict__ bmp)
{
    for (int idx = threadIdx.x; idx < D_*10*6; idx += 128) {
        int i  = idx / 60;
        int r  = idx - i*60;
        int k  = r / 6;
        int op = r - k*6;
        int o0 = 2*op, o1 = 2*op + 1;
        float w0, w1;
        if (k < 9) {
            w0 = Wh[(o0*D_ + i)*9 + k] + ((k == 4 && o0 == i) ? 1.f : 0.f);
            w1 = Wh[(o1*D_ + i)*9 + k] + ((k == 4 && o1 == i) ? 1.f : 0.f);
        } else {
            w0 = Wmp[o0*D_ + i];
            w1 = Wmp[o1*D_ + i];
        }
        g_wstage[idx] = pk2(w0, w1);
    }
    if (threadIdx.x < D_) g_bstage[threadIdx.x] = bh[threadIdx.x] + bmp[threadIdx.x];
}

// One NCA step: conv3x3 (+identity folded) + graph MP (10th tap) + elu.
// Round-14 body; weights fetched two channel-pairs at a time via
// 16-byte constant loads (ld.const.v2.u64) -> 30 weight loads/iter not 60.
__global__ void __launch_bounds__(128, 4) nca_step(
    const float* __restrict__ src, long long src_bs, int src_co,
    float* __restrict__ dst, long long dst_bs, int dst_co)
{
    __shared__ float tile[D_][SMH_][SMW_];   // input tile with 1-px halo

    const int tid = threadIdx.x;
    const int b   = blockIdx.z;
    const int bx0 = blockIdx.x * TX_;
    const int by0 = blockIdx.y * TY_;

    // ---- load input tile (+halo, zero-padded at image border) ----
    const float* sb = src + (long long)b * src_bs + (long long)src_co * N_;
    for (int idx = tid; idx < D_*SMH_*34; idx += 128) {
        int i  = idx / (SMH_*34);
        int r  = idx - i*(SMH_*34);
        int ly = r / 34;
        int lx = r - ly*34;
        int gy = by0 + ly - 1, gx = bx0 + lx - 1;
        float v = 0.f;
        if ((unsigned)gy < H_ && (unsigned)gx < W_)
            v = sb[(long long)i*N_ + gy*W_ + gx];
        tile[i][ly][lx] = v;
    }
    __syncthreads();

    // thread -> one row of 4 x-adjacent pixels: (gy, gx0..gx0+3)
    const int txp = tid & 7;        // 0..7
    const int typ = tid >> 3;       // 0..15
    const int gx0 = bx0 + 4*txp;
    const int gy  = by0 + typ;
    const int lxb = 4*txp;          // halo col of (gx0 - 1)

    float dinv[4];
    {
        int dy = (gy==0) + (gy==H_-1);
        #pragma unroll
        for (int p = 0; p < 4; p++) {
            int gx = gx0 + p;
            dinv[p] = 1.f / (float)(4 - dy - (gx==0) - (gx==W_-1));
        }
    }

    u64 acc[6][4];
    #pragma unroll
    for (int op = 0; op < 6; op++)
        #pragma unroll
        for (int p = 0; p < 4; p++) acc[op][p] = 0ull;

    #pragma unroll 1
    for (int i = 0; i < D_; i++) {
        const float* t0 = &tile[i][typ][lxb];
        float v0[6], v1[6], v2[6];
        #pragma unroll
        for (int c = 0; c < 6; c++) {
            v0[c] = t0[c];
            v1[c] = t0[SMW_ + c];
            v2[c] = t0[2*SMW_ + c];
        }
        // dup'd taps {v,v}
        u64 d0[6], d1[6], d2[6];
        #pragma unroll
        for (int c = 0; c < 6; c++) {
            d0[c] = pk2(v0[c], v0[c]);
            d1[c] = pk2(v1[c], v1[c]);
            d2[c] = pk2(v2[c], v2[c]);
        }
        u64 nsd[4];
        #pragma unroll
        for (int p = 0; p < 4; p++) {
            float ns = (v0[p+1] + v2[p+1] + v1[p] + v1[p+2]) * dinv[p];
            nsd[p] = pk2(ns, ns);
        }
        const ulonglong2* wq = reinterpret_cast<const ulonglong2*>(&c_w[i*60]);
        #pragma unroll
        for (int k = 0; k < 10; k++) {
            #pragma unroll
            for (int j = 0; j < 3; j++) {
                ulonglong2 w = wq[k*3 + j];      // 16B const load: 2 channel-pairs
                #pragma unroll
                for (int p = 0; p < 4; p++) {
                    u64 tap;
                    if      (k < 3) tap = d0[p + k];
                    else if (k < 6) tap = d1[p + k - 3];
                    else if (k < 9) tap = d2[p + k - 6];
                    else            tap = nsd[p];
                    fma2(acc[2*j  ][p], tap, w.x);
                    fma2(acc[2*j+1][p], tap, w.y);
                }
            }
        }
    }

    float* db = dst + (long long)b * dst_bs + (long long)dst_co * N_;
    #pragma unroll
    for (int op = 0; op < 6; op++) {
        float4 s0, s1;
        float b0 = c_b[2*op], b1 = c_b[2*op+1];
        float a, bb;
        upk2(acc[op][0], a, bb); s0.x = elu_f(a + b0); s1.x = elu_f(bb + b1);
        upk2(acc[op][1], a, bb); s0.y = elu_f(a + b0); s1.y = elu_f(bb + b1);
        upk2(acc[op][2], a, bb); s0.z = elu_f(a + b0); s1.z = elu_f(bb + b1);
        upk2(acc[op][3], a, bb); s0.w = elu_f(a + b0); s1.w = elu_f(bb + b1);
        *reinterpret_cast<float4*>(db + (long long)(2*op  )*N_ + gy*W_ + gx0) = s0;
        *reinterpret_cast<float4*>(db + (long long)(2*op+1)*N_ + gy*W_ + gx0) = s1;
    }
}

// Final head: reads hidden (out ch 4..15), computes alive + rgb, writes ch 0..3.
__global__ void __launch_bounds__(256) nca_head(
    float* __restrict__ out,
    const float* __restrict__ Wa, const float* __restrict__ ba,
    const float* __restrict__ Wr1, const float* __restrict__ br1,
    const float* __restrict__ Wr2, const float* __restrict__ br2)
{
    __shared__ float fsm[220];  // Wa(12) ba(1) Wr1(156) br1(12) Wr2(36) br2(3)
    const int tid = threadIdx.x;
    if (tid < 220) {
        float v;
        if (tid < 12)       v = Wa[tid];
        else if (tid == 12) v = ba[0];
        else if (tid < 169) v = Wr1[tid-13];
        else if (tid < 181) v = br1[tid-169];
        else if (tid < 217) v = Wr2[tid-181];
        else                v = br2[tid-217];
        fsm[tid] = v;
    }
    __syncthreads();

    long long pp = (long long)blockIdx.x * 256 + tid;   // pair index, < B*N/2
    int b = (int)(pp / (N_/2));
    int r = (int)(pp - (long long)b * (N_/2));
    float* base = out + (long long)b * 16 * N_ + 2*r;

    float h0[D_], h1[D_];
    #pragma unroll
    for (int c = 0; c < D_; c++) {
        float2 v = *reinterpret_cast<const float2*>(base + (long long)(4+c)*N_);
        h0[c] = v.x; h1[c] = v.y;
    }
    float al0 = fsm[12], al1 = fsm[12];
    #pragma unroll
    for (int c = 0; c < 12; c++) { al0 += fsm[c]*h0[c]; al1 += fsm[c]*h1[c]; }
    al0 = sigmoid_f(al0); al1 = sigmoid_f(al1);
    float r10[12], r11[12];
    #pragma unroll
    for (int j = 0; j < 12; j++) {
        float s0 = fsm[169+j], s1 = s0;
        #pragma unroll
        for (int c = 0; c < 12; c++) { s0 += fsm[13+j*13+c]*h0[c]; s1 += fsm[13+j*13+c]*h1[c]; }
        s0 += fsm[13+j*13+12]*al0;  s1 += fsm[13+j*13+12]*al1;
        r10[j] = s0 > 0.f ? s0 : 0.f;
        r11[j] = s1 > 0.f ? s1 : 0.f;
    }
    float2 sta; sta.x = al0; sta.y = al1;
    *reinterpret_cast<float2*>(base) = sta;              // channel 0: alive
    #pragma unroll
    for (int k = 0; k < 3; k++) {
        float s0 = fsm[217+k], s1 = s0;
        #pragma unroll
        for (int j = 0; j < 12; j++) { s0 += fsm[181+k*12+j]*r10[j]; s1 += fsm[181+k*12+j]*r11[j]; }
        s0 = sigmoid_f(s0)*al0;  s1 = sigmoid_f(s1)*al1;
        float2 st; st.x = s0; st.y = s1;
        *reinterpret_cast<float2*>(base + (long long)(1+k)*N_) = st;  // ch 1..3: rgb
    }
}

extern "C" void kernel_launch(void* const* d_in, const int* in_sizes, int n_in,
                              void* d_out, int out_size) {
    const float* x = (const float*)d_in[0];
    // locate weights by size: Wh has 12*12*9 = 1296 elements
    int wb = 1;
    while (wb < n_in && in_sizes[wb] != 1296) wb++;
    const float* Wh  = (const float*)d_in[wb+0];
    const float* bh  = (const float*)d_in[wb+1];
    const float* Wmp = (const float*)d_in[wb+2];
    const float* bmp = (const float*)d_in[wb+3];
    const float* Wa  = (const float*)d_in[wb+4];
    const float* ba  = (const float*)d_in[wb+5];
    const float* Wr1 = (const float*)d_in[wb+6];
    const float* br1 = (const float*)d_in[wb+7];
    const float* Wr2 = (const float*)d_in[wb+8];
    const float* br2 = (const float*)d_in[wb+9];
    float* out = (float*)d_out;

    float *bp0, *bp1;
    cudaGetSymbolAddress((void**)&bp0, g_buf0);
    cudaGetSymbolAddress((void**)&bp1, g_buf1);

    // pack weights once, then copy into the constant bank (D2D, graph-capturable)
    pack_weights<<<1, 128>>>(Wh, bh, Wmp, bmp);
    void* wstage; void* bstage;
    cudaGetSymbolAddress(&wstage, g_wstage);
    cudaGetSymbolAddress(&bstage, g_bstage);
    cudaMemcpyToSymbolAsync(c_w, wstage, sizeof(u64)*D_*10*6, 0, cudaMemcpyDeviceToDevice, 0);
    cudaMemcpyToSymbolAsync(c_b, bstage, sizeof(float)*D_, 0, cudaMemcpyDeviceToDevice, 0);

    dim3 grid(W_/TX_, H_/TY_, B_);
    dim3 blk(128);

    const float* src = x;
    long long sbs = 16LL*N_; int sco = 4;
    for (int s = 0; s < STEPS_; s++) {
        int fin = (s == STEPS_-1);
        float* dst; long long dbs; int dco;
        if (fin) { dst = out; dbs = 16LL*N_; dco = 4; }
        else     { dst = (s & 1) ? bp1 : bp0; dbs = 12LL*N_; dco = 0; }
        nca_step<<<grid, blk>>>(src, sbs, sco, dst, dbs, dco);
        src = dst; sbs = dbs; sco = dco;
    }
    // head epilogue: fills out channels 0..3 from hidden in channels 4..15
    nca_head<<<(B_*N_/2)/256, 256>>>(out, Wa, ba, Wr1, br1, Wr2, br2);
}